// round 1
// baseline (speedup 1.0000x reference)
#include <cuda_runtime.h>
#include <math.h>

#define BB 128
#define TT 512
#define DD 128
#define HH 384
#define GG 1542
#define CONVW 10
#define HSS 64
#define KI (CONVW * HH) /* 3840 */

// ---------------- static device scratch (no allocations allowed) ----------------
__device__ float g_xk[TT * BB * GG];      // [t*B+b, G]  (~404 MB)
__device__ float g_xout[BB * GG];         // per-step pre-activations
__device__ float g_h[TT * BB * HH];       // h_t for all t (~100 MB)
__device__ float g_c[BB * HH];            // cell state
__device__ float g_dist[TT * BB];         // cur_dist per step
__device__ float g_dis[TT * BB * CONVW];  // local_dis per step
__device__ float g_wct[KI * HH];          // Wc transposed: [(k*H+i), o]
__device__ float g_conv[TT * BB * HH];    // conv output (+bc)
__device__ unsigned g_bar_cnt;
__device__ volatile unsigned g_bar_gen;

// ---------------- grid barrier (all blocks co-resident) ----------------
__device__ __forceinline__ void grid_barrier(unsigned nb) {
    __syncthreads();
    if (threadIdx.x == 0) {
        __threadfence();
        unsigned gen = g_bar_gen;
        if (atomicAdd(&g_bar_cnt, 1u) == nb - 1u) {
            g_bar_cnt = 0u;
            __threadfence();
            g_bar_gen = gen + 1u;
        } else {
            while (g_bar_gen == gen) { }
        }
        __threadfence();
    }
    __syncthreads();
}

// ---------------- K_wct: transpose Wc[o,i,k] -> g_wct[(k*H+i)*H + o] ----------------
__global__ void k_wct(const float* __restrict__ Wc) {
    int idx = blockIdx.x * 256 + threadIdx.x;
    if (idx >= KI * HH) return;
    int o = idx % HH;
    int rest = idx / HH;      // k*HH + i
    int i = rest % HH;
    int k = rest / HH;
    g_wct[idx] = Wc[((size_t)o * HH + i) * CONVW + k];
}

// ---------------- K1: Xk = [x,1]@Wk + bk.  M=T*B, K=128, N=G ----------------
__global__ void __launch_bounds__(256) k1_xk(const float* __restrict__ x,
                                             const float* __restrict__ Wk,
                                             const float* __restrict__ bk) {
    __shared__ float As[64][17];   // [rm][kk]
    __shared__ float Bs[16][64];   // [kk][cn]
    const int tid = threadIdx.x;
    const int r0 = blockIdx.y * 64;
    const int g0 = blockIdx.x * 64;
    const int tr = tid >> 4, tc = tid & 15;
    float acc[4][4] = {};
    for (int k0 = 0; k0 < DD; k0 += 16) {
#pragma unroll
        for (int p = 0; p < 4; ++p) {
            int lin = tid + p * 256;
            int kk = lin & 15, rm = lin >> 4;
            int r = r0 + rm;
            int t = r >> 7, b = r & 127;
            As[rm][kk] = x[((size_t)b * TT + t) * DD + k0 + kk];
            int cn = lin & 63, kk2 = lin >> 6;
            int g = g0 + cn;
            Bs[kk2][cn] = (g < GG) ? Wk[(size_t)(k0 + kk2) * GG + g] : 0.f;
        }
        __syncthreads();
#pragma unroll
        for (int kk = 0; kk < 16; ++kk) {
            float a[4], bv[4];
#pragma unroll
            for (int i = 0; i < 4; ++i) a[i] = As[tr + 16 * i][kk];
#pragma unroll
            for (int j = 0; j < 4; ++j) bv[j] = Bs[kk][tc + 16 * j];
#pragma unroll
            for (int i = 0; i < 4; ++i)
#pragma unroll
                for (int j = 0; j < 4; ++j) acc[i][j] += a[i] * bv[j];
        }
        __syncthreads();
    }
#pragma unroll
    for (int i = 0; i < 4; ++i) {
        int r = r0 + tr + 16 * i;
#pragma unroll
        for (int j = 0; j < 4; ++j) {
            int g = g0 + tc + 16 * j;
            if (g < GG)
                g_xk[(size_t)r * GG + g] = acc[i][j] + Wk[(size_t)DD * GG + g] + bk[g];
        }
    }
}

// ---------------- K2: persistent recurrent scan ----------------
// 136 blocks = 8 row-tiles (16 b) x 17 col-tiles (96 g)
__global__ void __launch_bounds__(256) k2_recurrent(const float* __restrict__ Wr,
                                                    const float* __restrict__ br) {
    const int tid = threadIdx.x;
    const int bid = blockIdx.x;
    const int rt = bid / 17, ct = bid % 17;
    const int b0 = rt * 16, g0 = ct * 96;
    __shared__ float As[16][17];   // [kk][rr]
    __shared__ float Bs[16][96];   // [kk][cc]

    // zero cell state
    for (int i = bid * 256 + tid; i < BB * HH; i += 136 * 256) g_c[i] = 0.f;
    grid_barrier(136);

    const int tr = tid >> 5;   // 0..7  -> 2 rows each
    const int tc = tid & 31;   // 0..31 -> 3 cols each
    const int lkk = tid & 15, lrr = tid >> 4;

    for (int t = 0; t < TT; ++t) {
        float acc[2][3] = {};
        if (t > 0) {
            const float* hp = g_h + (size_t)(t - 1) * BB * HH;
            for (int k0 = 0; k0 < HH; k0 += 16) {
                As[lkk][lrr] = __ldcg(&hp[(size_t)(b0 + lrr) * HH + k0 + lkk]);
#pragma unroll
                for (int l = 0; l < 6; ++l) {
                    int lin = tid + l * 256;
                    int cc = lin % 96, kk = lin / 96;
                    int g = g0 + cc;
                    Bs[kk][cc] = (g < GG) ? Wr[(size_t)(k0 + kk) * GG + g] : 0.f;
                }
                __syncthreads();
#pragma unroll
                for (int kk = 0; kk < 16; ++kk) {
                    float a0 = As[kk][tr * 2 + 0];
                    float a1 = As[kk][tr * 2 + 1];
                    float b0v = Bs[kk][tc * 3 + 0];
                    float b1v = Bs[kk][tc * 3 + 1];
                    float b2v = Bs[kk][tc * 3 + 2];
                    acc[0][0] += a0 * b0v; acc[0][1] += a0 * b1v; acc[0][2] += a0 * b2v;
                    acc[1][0] += a1 * b0v; acc[1][1] += a1 * b1v; acc[1][2] += a1 * b2v;
                }
                __syncthreads();
            }
        }
        // epilogue: + bias-row of Wr + br + Xk
        const float* xkrow = g_xk + (size_t)t * BB * GG;
#pragma unroll
        for (int i = 0; i < 2; ++i) {
            int b = b0 + tr * 2 + i;
#pragma unroll
            for (int j = 0; j < 3; ++j) {
                int g = g0 + tc * 3 + j;
                if (g < GG) {
                    float v = acc[i][j] + Wr[(size_t)HH * GG + g] + br[g]
                              + xkrow[(size_t)b * GG + g];
                    g_xout[b * GG + g] = v;
                }
            }
        }
        grid_barrier(136);

        // elementwise: block b handles batch row b
        if (bid < BB) {
            const int b = bid;
            const float* row = g_xout + b * GG;
            float m0 = __ldcg(&row[0]), m1 = __ldcg(&row[1]), m2 = __ldcg(&row[2]);
            float n0 = __ldcg(&row[3]), n1 = __ldcg(&row[4]), n2 = __ldcg(&row[5]);
            float mx = fmaxf(m0, fmaxf(m1, m2));
            float e0 = expf(m0 - mx), e1 = expf(m1 - mx), e2 = expf(m2 - mx);
            float inv = 1.f / (e0 + e1 + e2);
            float f0 = e0 * inv, f1 = (e0 + e1) * inv, f2 = 1.f;   // l2r cumsum
            mx = fmaxf(n0, fmaxf(n1, n2));
            e0 = expf(n0 - mx); e1 = expf(n1 - mx); e2 = expf(n2 - mx);
            inv = 1.f / (e0 + e1 + e2);
            float i2 = e2 * inv, i1 = (e1 + e2) * inv, i0 = 1.f;   // r2l cumsum
            if (tid == 0) g_dist[t * BB + b] = 1.f - (f0 + f1 + f2) * (1.f / 3.f);
            for (int idx = tid; idx < HH; idx += 256) {
                int l = idx >> 7;
                int c127 = idx & 127;
                float fm = (l == 0) ? f0 : ((l == 1) ? f1 : f2);
                float im = (l == 0) ? i0 : ((l == 1) ? i1 : i2);
                float ov = fm * im;
                float gf = __ldcg(&row[6 + l * 128 + c127]);
                float gi = __ldcg(&row[6 + (3 + l) * 128 + c127]);
                float go = __ldcg(&row[6 + (6 + l) * 128 + c127]);
                float gc = __ldcg(&row[6 + (9 + l) * 128 + c127]);
                float fg = 1.f / (1.f + expf(-gf));
                float ig = 1.f / (1.f + expf(-gi));
                float og = 1.f / (1.f + expf(-go));
                float ci = tanhf(gc);
                float cl = g_c[b * HH + idx];
                float cn = (ov * fg + fm - ov) * cl + (ov * ig + im - ov) * ci;
                float hn = og * tanhf(cn);
                g_c[b * HH + idx] = cn;
                g_h[(size_t)t * BB * HH + (size_t)b * HH + idx] = hn;
            }
        }
        grid_barrier(136);
    }
}

// ---------------- K_dis: local_dis = softmax(cumsum(window of cur_dist)) ----------------
__global__ void k_dis() {
    int idx = blockIdx.x * 256 + threadIdx.x;
    if (idx >= TT * BB) return;
    int t = idx >> 7, b = idx & 127;
    float c[CONVW];
    float cum = 0.f;
#pragma unroll
    for (int k = 0; k < CONVW; ++k) {
        int s = t - (CONVW - 1) + k;
        float d = (s >= 0) ? g_dist[s * BB + b] : 0.f;
        cum += d;
        c[k] = cum;
    }
    float mx = c[0];
#pragma unroll
    for (int k = 1; k < CONVW; ++k) mx = fmaxf(mx, c[k]);
    float sum = 0.f;
#pragma unroll
    for (int k = 0; k < CONVW; ++k) { c[k] = expf(c[k] - mx); sum += c[k]; }
    float inv = 1.f / sum;
#pragma unroll
    for (int k = 0; k < CONVW; ++k) g_dis[(size_t)idx * CONVW + k] = c[k] * inv;
}

// ---------------- K3: conv GEMM. M=T*B, K=3840 (k,i), N=384 ----------------
__global__ void __launch_bounds__(256) k3_conv(const float* __restrict__ bc) {
    __shared__ float As[64][17];      // [rm][kk]
    __shared__ float Bs[16][64];      // [kk][cn]
    __shared__ float s_dis[64][10];
    const int tid = threadIdx.x;
    const int r0 = blockIdx.y * 64;
    const int o0 = blockIdx.x * 64;
    const int t = r0 >> 7;
    const int b0 = r0 & 127;
    for (int lin = tid; lin < 640; lin += 256) {
        int rr = lin / 10, k = lin % 10;
        s_dis[rr][k] = g_dis[((size_t)t * BB + b0 + rr) * CONVW + k];
    }
    __syncthreads();
    const int tr = tid >> 4, tc = tid & 15;
    float acc[4][4] = {};
    for (int kb = 0; kb < KI; kb += 16) {
#pragma unroll
        for (int p = 0; p < 4; ++p) {
            int lin = tid + p * 256;
            int kk = lin & 15, rm = lin >> 4;
            int ki = kb + kk;
            int k = ki / HH;
            int i = ki - k * HH;
            int s = t - (CONVW - 1) + k;
            float v = 0.f;
            if (s >= 0)
                v = s_dis[rm][k] * g_h[((size_t)s * BB + b0 + rm) * HH + i];
            As[rm][kk] = v;
            int cn = lin & 63, kk2 = lin >> 6;
            Bs[kk2][cn] = g_wct[(size_t)(kb + kk2) * HH + o0 + cn];
        }
        __syncthreads();
#pragma unroll
        for (int kk = 0; kk < 16; ++kk) {
            float a[4], bv[4];
#pragma unroll
            for (int i = 0; i < 4; ++i) a[i] = As[tr + 16 * i][kk];
#pragma unroll
            for (int j = 0; j < 4; ++j) bv[j] = Bs[kk][tc + 16 * j];
#pragma unroll
            for (int i = 0; i < 4; ++i)
#pragma unroll
                for (int j = 0; j < 4; ++j) acc[i][j] += a[i] * bv[j];
        }
        __syncthreads();
    }
#pragma unroll
    for (int i = 0; i < 4; ++i) {
        int r = r0 + tr + 16 * i;
#pragma unroll
        for (int j = 0; j < 4; ++j) {
            int o = o0 + tc + 16 * j;
            g_conv[(size_t)r * HH + o] = acc[i][j] + bc[o];
        }
    }
}

// ---------------- K4: theme MLP + final output ----------------
__global__ void __launch_bounds__(256) k4_out(const float* __restrict__ Ws,
                                              const float* __restrict__ bs,
                                              const float* __restrict__ Wrs,
                                              const float* __restrict__ brs,
                                              float* __restrict__ out) {
    __shared__ float s_mh[16][HH];
    __shared__ float s_q[16][HSS];
    __shared__ float s_dis2[16][10];
    const int tid = threadIdx.x;
    const int r0 = blockIdx.x * 16;
    const int t = r0 >> 7, b0 = r0 & 127;
    for (int lin = tid; lin < 160; lin += 256) {
        int rr = lin / 10, k = lin % 10;
        s_dis2[rr][k] = g_dis[(size_t)(r0 + rr) * CONVW + k];
    }
    __syncthreads();
    // mean_h = (1/CONV) * sum_k dis_k * h_{t-9+k}
    for (int idx = tid; idx < 16 * HH; idx += 256) {
        int rr = idx / HH, i = idx - rr * HH;
        float acc = 0.f;
#pragma unroll
        for (int k = 0; k < CONVW; ++k) {
            int s = t - (CONVW - 1) + k;
            if (s >= 0)
                acc += s_dis2[rr][k] * g_h[((size_t)s * BB + b0 + rr) * HH + i];
        }
        s_mh[rr][i] = acc * (1.f / CONVW);
    }
    __syncthreads();
    // q = relu(mean_h @ Ws + bs)
    for (int idx = tid; idx < 16 * HSS; idx += 256) {
        int rr = idx >> 6, j = idx & 63;
        float acc = bs[j];
        for (int i = 0; i < HH; ++i) acc += s_mh[rr][i] * Ws[i * HSS + j];
        s_q[rr][j] = fmaxf(acc, 0.f);
    }
    __syncthreads();
    // theme = sigmoid(q @ Wrs + brs); out = theme*conv + h_t
    for (int idx = tid; idx < 16 * HH; idx += 256) {
        int rr = idx / HH, o = idx - rr * HH;
        float acc = brs[o];
#pragma unroll 8
        for (int j = 0; j < HSS; ++j) acc += s_q[rr][j] * Wrs[j * HH + o];
        float theme = 1.f / (1.f + expf(-acc));
        int r = r0 + rr;
        int b = b0 + rr;
        out[((size_t)b * TT + t) * HH + o] =
            theme * g_conv[(size_t)r * HH + o] + g_h[((size_t)t * BB + b) * HH + o];
    }
}

// ---------------- entry ----------------
extern "C" void kernel_launch(void* const* d_in, const int* in_sizes, int n_in,
                              void* d_out, int out_size) {
    (void)in_sizes; (void)n_in; (void)out_size;
    const float* x   = (const float*)d_in[0];
    // d_in[1] = lengths (unused by forward)
    const float* Wk  = (const float*)d_in[2];
    const float* bk  = (const float*)d_in[3];
    const float* Wr  = (const float*)d_in[4];
    const float* br  = (const float*)d_in[5];
    const float* Ws  = (const float*)d_in[6];
    const float* bs  = (const float*)d_in[7];
    const float* Wrs = (const float*)d_in[8];
    const float* brs = (const float*)d_in[9];
    const float* Wc  = (const float*)d_in[10];
    const float* bc  = (const float*)d_in[11];
    float* out = (float*)d_out;

    k_wct<<<(KI * HH + 255) / 256, 256>>>(Wc);
    k1_xk<<<dim3(25, 1024), 256>>>(x, Wk, bk);
    k2_recurrent<<<136, 256>>>(Wr, br);
    k_dis<<<(TT * BB + 255) / 256, 256>>>();
    k3_conv<<<dim3(6, 1024), 256>>>(bc);
    k4_out<<<4096, 256>>>(Ws, bs, Wrs, brs, out);
}

// round 3
// speedup vs baseline: 1.2181x; 1.2181x over previous
#include <cuda_runtime.h>
#include <cuda_bf16.h>
#include <cstdint>
#include <math.h>

#define BB 128
#define TT 512
#define DD 128
#define HH 384
#define GG 1542
#define CONVW 10
#define HSS 64
#define NR (TT * BB)          /* 65536 rows */
#define NN 3840               /* N = CONVW * HH */
#define KK 1152               /* K = 3 * HH (bf16 split) */

// ---------------- static device scratch ----------------
__device__ float g_xk[(size_t)NR * GG];       // [t*B+b, G]
__device__ float g_xout[BB * GG];
__device__ float g_h[(size_t)NR * HH];        // h_t
__device__ float g_c[BB * HH];
__device__ float g_dist[NR];
__device__ float g_dis[NR * CONVW];
__device__ float g_conv[(size_t)NR * HH];
__device__ float g_A[(size_t)NR * NN];        // A_all (fp32)
__device__ __nv_bfloat16 g_hhi[(size_t)NR * HH];
__device__ __nv_bfloat16 g_hlo[(size_t)NR * HH];
__device__ __nv_bfloat16 g_wbT[(size_t)NN * KK];  // B operand [n, kc] K-major
__device__ unsigned g_bar_cnt;
__device__ volatile unsigned g_bar_gen;

// ---------------- helpers ----------------
__device__ __forceinline__ uint32_t smem_u32(const void* p) {
    uint32_t a;
    asm("{ .reg .u64 t; cvta.to.shared.u64 t, %1; cvt.u32.u64 %0, t; }" : "=r"(a) : "l"(p));
    return a;
}

// ---------------- grid barrier ----------------
__device__ __forceinline__ void grid_barrier(unsigned nb) {
    __syncthreads();
    if (threadIdx.x == 0) {
        __threadfence();
        unsigned gen = g_bar_gen;
        if (atomicAdd(&g_bar_cnt, 1u) == nb - 1u) {
            g_bar_cnt = 0u;
            __threadfence();
            g_bar_gen = gen + 1u;
        } else {
            while (g_bar_gen == gen) { }
        }
        __threadfence();
    }
    __syncthreads();
}

// ---------------- K1: Xk = [x,1]@Wk + bk ----------------
__global__ void __launch_bounds__(256) k1_xk(const float* __restrict__ x,
                                             const float* __restrict__ Wk,
                                             const float* __restrict__ bk) {
    __shared__ float As[64][17];
    __shared__ float Bs[16][64];
    const int tid = threadIdx.x;
    const int r0 = blockIdx.y * 64;
    const int g0 = blockIdx.x * 64;
    const int tr = tid >> 4, tc = tid & 15;
    float acc[4][4] = {};
    for (int k0 = 0; k0 < DD; k0 += 16) {
#pragma unroll
        for (int p = 0; p < 4; ++p) {
            int lin = tid + p * 256;
            int kk = lin & 15, rm = lin >> 4;
            int r = r0 + rm;
            int t = r >> 7, b = r & 127;
            As[rm][kk] = x[((size_t)b * TT + t) * DD + k0 + kk];
            int cn = lin & 63, kk2 = lin >> 6;
            int g = g0 + cn;
            Bs[kk2][cn] = (g < GG) ? Wk[(size_t)(k0 + kk2) * GG + g] : 0.f;
        }
        __syncthreads();
#pragma unroll
        for (int kk = 0; kk < 16; ++kk) {
            float a[4], bv[4];
#pragma unroll
            for (int i = 0; i < 4; ++i) a[i] = As[tr + 16 * i][kk];
#pragma unroll
            for (int j = 0; j < 4; ++j) bv[j] = Bs[kk][tc + 16 * j];
#pragma unroll
            for (int i = 0; i < 4; ++i)
#pragma unroll
                for (int j = 0; j < 4; ++j) acc[i][j] += a[i] * bv[j];
        }
        __syncthreads();
    }
#pragma unroll
    for (int i = 0; i < 4; ++i) {
        int r = r0 + tr + 16 * i;
#pragma unroll
        for (int j = 0; j < 4; ++j) {
            int g = g0 + tc + 16 * j;
            if (g < GG)
                g_xk[(size_t)r * GG + g] = acc[i][j] + Wk[(size_t)DD * GG + g] + bk[g];
        }
    }
}

// ---------------- K2: persistent recurrent scan ----------------
__global__ void __launch_bounds__(256) k2_recurrent(const float* __restrict__ Wr,
                                                    const float* __restrict__ br) {
    const int tid = threadIdx.x;
    const int bid = blockIdx.x;
    const int rt = bid / 17, ct = bid % 17;
    const int b0 = rt * 16, g0 = ct * 96;
    __shared__ float As[16][17];
    __shared__ float Bs[16][96];

    for (int i = bid * 256 + tid; i < BB * HH; i += 136 * 256) g_c[i] = 0.f;
    grid_barrier(136);

    const int tr = tid >> 5;
    const int tc = tid & 31;
    const int lkk = tid & 15, lrr = tid >> 4;

    for (int t = 0; t < TT; ++t) {
        float acc[2][3] = {};
        if (t > 0) {
            const float* hp = g_h + (size_t)(t - 1) * BB * HH;
            for (int k0 = 0; k0 < HH; k0 += 16) {
                As[lkk][lrr] = __ldcg(&hp[(size_t)(b0 + lrr) * HH + k0 + lkk]);
#pragma unroll
                for (int l = 0; l < 6; ++l) {
                    int lin = tid + l * 256;
                    int cc = lin % 96, kk = lin / 96;
                    int g = g0 + cc;
                    Bs[kk][cc] = (g < GG) ? Wr[(size_t)(k0 + kk) * GG + g] : 0.f;
                }
                __syncthreads();
#pragma unroll
                for (int kk = 0; kk < 16; ++kk) {
                    float a0 = As[kk][tr * 2 + 0];
                    float a1 = As[kk][tr * 2 + 1];
                    float b0v = Bs[kk][tc * 3 + 0];
                    float b1v = Bs[kk][tc * 3 + 1];
                    float b2v = Bs[kk][tc * 3 + 2];
                    acc[0][0] += a0 * b0v; acc[0][1] += a0 * b1v; acc[0][2] += a0 * b2v;
                    acc[1][0] += a1 * b0v; acc[1][1] += a1 * b1v; acc[1][2] += a1 * b2v;
                }
                __syncthreads();
            }
        }
        const float* xkrow = g_xk + (size_t)t * BB * GG;
#pragma unroll
        for (int i = 0; i < 2; ++i) {
            int b = b0 + tr * 2 + i;
#pragma unroll
            for (int j = 0; j < 3; ++j) {
                int g = g0 + tc * 3 + j;
                if (g < GG) {
                    float v = acc[i][j] + Wr[(size_t)HH * GG + g] + br[g]
                              + xkrow[(size_t)b * GG + g];
                    g_xout[b * GG + g] = v;
                }
            }
        }
        grid_barrier(136);

        if (bid < BB) {
            const int b = bid;
            const float* row = g_xout + b * GG;
            float m0 = __ldcg(&row[0]), m1 = __ldcg(&row[1]), m2 = __ldcg(&row[2]);
            float n0 = __ldcg(&row[3]), n1 = __ldcg(&row[4]), n2 = __ldcg(&row[5]);
            float mx = fmaxf(m0, fmaxf(m1, m2));
            float e0 = expf(m0 - mx), e1 = expf(m1 - mx), e2 = expf(m2 - mx);
            float inv = 1.f / (e0 + e1 + e2);
            float f0 = e0 * inv, f1 = (e0 + e1) * inv, f2 = 1.f;
            mx = fmaxf(n0, fmaxf(n1, n2));
            e0 = expf(n0 - mx); e1 = expf(n1 - mx); e2 = expf(n2 - mx);
            inv = 1.f / (e0 + e1 + e2);
            float i2 = e2 * inv, i1 = (e1 + e2) * inv, i0 = 1.f;
            if (tid == 0) g_dist[t * BB + b] = 1.f - (f0 + f1 + f2) * (1.f / 3.f);
            for (int idx = tid; idx < HH; idx += 256) {
                int l = idx >> 7;
                int c127 = idx & 127;
                float fm = (l == 0) ? f0 : ((l == 1) ? f1 : f2);
                float im = (l == 0) ? i0 : ((l == 1) ? i1 : i2);
                float ov = fm * im;
                float gf = __ldcg(&row[6 + l * 128 + c127]);
                float gi = __ldcg(&row[6 + (3 + l) * 128 + c127]);
                float go = __ldcg(&row[6 + (6 + l) * 128 + c127]);
                float gc = __ldcg(&row[6 + (9 + l) * 128 + c127]);
                float fg = 1.f / (1.f + expf(-gf));
                float ig = 1.f / (1.f + expf(-gi));
                float og = 1.f / (1.f + expf(-go));
                float ci = tanhf(gc);
                float cl = g_c[b * HH + idx];
                float cn = (ov * fg + fm - ov) * cl + (ov * ig + im - ov) * ci;
                float hn = og * tanhf(cn);
                g_c[b * HH + idx] = cn;
                g_h[(size_t)t * BB * HH + (size_t)b * HH + idx] = hn;
            }
        }
        grid_barrier(136);
    }
}

// ---------------- K_dis ----------------
__global__ void k_dis() {
    int idx = blockIdx.x * 256 + threadIdx.x;
    if (idx >= NR) return;
    int t = idx >> 7, b = idx & 127;
    float c[CONVW];
    float cum = 0.f;
#pragma unroll
    for (int k = 0; k < CONVW; ++k) {
        int s = t - (CONVW - 1) + k;
        float d = (s >= 0) ? g_dist[s * BB + b] : 0.f;
        cum += d;
        c[k] = cum;
    }
    float mx = c[0];
#pragma unroll
    for (int k = 1; k < CONVW; ++k) mx = fmaxf(mx, c[k]);
    float sum = 0.f;
#pragma unroll
    for (int k = 0; k < CONVW; ++k) { c[k] = expf(c[k] - mx); sum += c[k]; }
    float inv = 1.f / sum;
#pragma unroll
    for (int k = 0; k < CONVW; ++k) g_dis[(size_t)idx * CONVW + k] = c[k] * inv;
}

// ---------------- prep: split h into bf16 hi/lo ----------------
__global__ void __launch_bounds__(256) k_split_h() {
    size_t idx = (size_t)blockIdx.x * 256 + threadIdx.x;   // float4 index
    if (idx >= (size_t)NR * HH / 4) return;
    float4 v = reinterpret_cast<const float4*>(g_h)[idx];
    __nv_bfloat16 h0 = __float2bfloat16(v.x);
    __nv_bfloat16 h1 = __float2bfloat16(v.y);
    __nv_bfloat16 h2 = __float2bfloat16(v.z);
    __nv_bfloat16 h3 = __float2bfloat16(v.w);
    __nv_bfloat162* hi = reinterpret_cast<__nv_bfloat162*>(g_hhi) + idx * 2;
    hi[0] = __nv_bfloat162(h0, h1);
    hi[1] = __nv_bfloat162(h2, h3);
    __nv_bfloat16 l0 = __float2bfloat16(v.x - __bfloat162float(h0));
    __nv_bfloat16 l1 = __float2bfloat16(v.y - __bfloat162float(h1));
    __nv_bfloat16 l2 = __float2bfloat16(v.z - __bfloat162float(h2));
    __nv_bfloat16 l3 = __float2bfloat16(v.w - __bfloat162float(h3));
    __nv_bfloat162* lo = reinterpret_cast<__nv_bfloat162*>(g_hlo) + idx * 2;
    lo[0] = __nv_bfloat162(l0, l1);
    lo[1] = __nv_bfloat162(l2, l3);
}

// ---------------- prep: B operand from Wc ----------------
// g_wbT[n][kc], n = k*HH+o, kc = p*HH+i, value = (p==1 ? lo : hi)(Wc[o,i,k])
__global__ void __launch_bounds__(256) k_prep_w(const float* __restrict__ Wc) {
    size_t idx = (size_t)blockIdx.x * 256 + threadIdx.x;
    if (idx >= (size_t)NN * KK) return;
    int kc = (int)(idx % KK);
    int n  = (int)(idx / KK);
    int p = kc / HH, i = kc - p * HH;
    int k = n / HH, o = n - k * HH;
    float w = Wc[((size_t)o * HH + i) * CONVW + k];
    __nv_bfloat16 hi = __float2bfloat16(w);
    __nv_bfloat16 val = (p == 1) ? __float2bfloat16(w - __bfloat162float(hi)) : hi;
    g_wbT[idx] = val;
}

// ---------------- K3 GEMM via mma.sync bf16 ----------------
// CTA tile 128(M) x 128(N), K-step 32, 8 warps (2x4), warp tile 64x32.
// smem: 2 stages x { A 128x40 b16 | B 128x40 b16 } = 40960 B.
#define KSTEP 32
#define NCH (KK / KSTEP)   /* 36 */
#define ROWB 80            /* padded row stride in bytes (40 b16) */

__device__ __forceinline__ void cp16(uint32_t s, const void* g) {
    asm volatile("cp.async.cg.shared.global [%0], [%1], 16;" :: "r"(s), "l"(g));
}

__global__ void __launch_bounds__(256, 2) k3_gemm() {
    __shared__ __align__(128) char sbuf[2][2 * 128 * ROWB];
    const int tid = threadIdx.x;
    const int wid = tid >> 5;
    const int lane = tid & 31;
    const int wm = wid >> 2;          // 0..1
    const int wn = wid & 3;           // 0..3
    const int n0 = blockIdx.x * 128;
    const size_t r0 = (size_t)blockIdx.y * 128;

    // global load mapping: thread -> (row = tid>>1, half = tid&1), 2x16B each
    const int grow = tid >> 1;
    const int ghalf = tid & 1;

    uint32_t sA[2], sB[2];
#pragma unroll
    for (int s = 0; s < 2; ++s) {
        sA[s] = smem_u32(&sbuf[s][0]);
        sB[s] = smem_u32(&sbuf[s][128 * ROWB]);
    }

    // ldmatrix per-lane offsets
    const int q4 = lane >> 3;                       // 0..3
    const uint32_t aoff = (uint32_t)(((q4 & 1) * 8 + (lane & 7)) * ROWB + (q4 >> 1) * 16);
    const uint32_t boff = (uint32_t)((lane & 7) * ROWB + ((lane >> 3) & 1) * 16);

    auto issue = [&](int ch) {
        const int kb = ch * KSTEP;
        const int p = kb / HH;
        const int i0 = kb - p * HH;
        const __nv_bfloat16* hsrc = (p == 2) ? g_hlo : g_hhi;
        const int buf = ch & 1;
        // A: row grow, 16B chunks
        const __nv_bfloat16* ga = hsrc + (r0 + grow) * HH + i0 + ghalf * 16;
        uint32_t da = sA[buf] + grow * ROWB + ghalf * 32;
        cp16(da, ga);
        cp16(da + 16, ga + 8);
        // B
        const __nv_bfloat16* gb = g_wbT + (size_t)(n0 + grow) * KK + kb + ghalf * 16;
        uint32_t db = sB[buf] + grow * ROWB + ghalf * 32;
        cp16(db, gb);
        cp16(db + 16, gb + 8);
        asm volatile("cp.async.commit_group;");
    };

    issue(0);
    issue(1);

    float c[4][4][4] = {};

    for (int ch = 0; ch < NCH; ++ch) {
        if (ch == NCH - 1) asm volatile("cp.async.wait_group 0;");
        else               asm volatile("cp.async.wait_group 1;");
        __syncthreads();
        const int buf = ch & 1;
        const uint32_t abase = sA[buf] + (wm * 64) * ROWB + aoff;
        const uint32_t bbase = sB[buf] + (wn * 32) * ROWB + boff;
#pragma unroll
        for (int s = 0; s < 2; ++s) {
            uint32_t a[4][4];
#pragma unroll
            for (int i = 0; i < 4; ++i) {
                uint32_t ad = abase + i * 16 * ROWB + s * 32;
                asm volatile("ldmatrix.sync.aligned.m8n8.x4.shared.b16 {%0,%1,%2,%3}, [%4];"
                             : "=r"(a[i][0]), "=r"(a[i][1]), "=r"(a[i][2]), "=r"(a[i][3])
                             : "r"(ad));
            }
            uint32_t bfr[4][2];
#pragma unroll
            for (int j = 0; j < 4; ++j) {
                uint32_t bd = bbase + j * 8 * ROWB + s * 32;
                asm volatile("ldmatrix.sync.aligned.m8n8.x2.shared.b16 {%0,%1}, [%2];"
                             : "=r"(bfr[j][0]), "=r"(bfr[j][1]) : "r"(bd));
            }
#pragma unroll
            for (int i = 0; i < 4; ++i)
#pragma unroll
                for (int j = 0; j < 4; ++j) {
                    asm volatile(
                        "mma.sync.aligned.m16n8k16.row.col.f32.bf16.bf16.f32 "
                        "{%0,%1,%2,%3}, {%4,%5,%6,%7}, {%8,%9}, {%0,%1,%2,%3};"
                        : "+f"(c[i][j][0]), "+f"(c[i][j][1]), "+f"(c[i][j][2]), "+f"(c[i][j][3])
                        : "r"(a[i][0]), "r"(a[i][1]), "r"(a[i][2]), "r"(a[i][3]),
                          "r"(bfr[j][0]), "r"(bfr[j][1]));
                }
        }
        __syncthreads();
        if (ch + 2 < NCH) issue(ch + 2);
    }

    // epilogue
    const int gq = lane >> 2;        // 0..7
    const int t4 = lane & 3;         // 0..3
#pragma unroll
    for (int i = 0; i < 4; ++i) {
        size_t row = r0 + wm * 64 + i * 16 + gq;
        float* dst0 = g_A + row * NN + n0 + wn * 32 + t4 * 2;
        float* dst1 = g_A + (row + 8) * NN + n0 + wn * 32 + t4 * 2;
#pragma unroll
        for (int j = 0; j < 4; ++j) {
            *reinterpret_cast<float2*>(dst0 + j * 8) = make_float2(c[i][j][0], c[i][j][1]);
            *reinterpret_cast<float2*>(dst1 + j * 8) = make_float2(c[i][j][2], c[i][j][3]);
        }
    }
}

// ---------------- gather: conv = sum_k dis * A_all ----------------
__global__ void __launch_bounds__(256) k_gather(const float* __restrict__ bc) {
    size_t idx = (size_t)blockIdx.x * 256 + threadIdx.x;  // (t,b,o)
    if (idx >= (size_t)NR * HH) return;
    int o = (int)(idx % HH);
    int r = (int)(idx / HH);       // t*128+b
    int t = r >> 7, b = r & 127;
    const float* dis = g_dis + (size_t)r * CONVW;
    float acc = bc[o];
    int kmin = (t >= CONVW - 1) ? 0 : (CONVW - 1 - t);
#pragma unroll
    for (int k = 0; k < CONVW; ++k) {
        if (k >= kmin) {
            int s = t - (CONVW - 1) + k;
            acc += dis[k] * g_A[((size_t)s * BB + b) * NN + (size_t)k * HH + o];
        }
    }
    g_conv[(size_t)r * HH + o] = acc;
}

// ---------------- K4: theme MLP + final output ----------------
__global__ void __launch_bounds__(256) k4_out(const float* __restrict__ Ws,
                                              const float* __restrict__ bs,
                                              const float* __restrict__ Wrs,
                                              const float* __restrict__ brs,
                                              float* __restrict__ out) {
    __shared__ float s_mh[16][HH];
    __shared__ float s_q[16][HSS];
    __shared__ float s_dis2[16][10];
    const int tid = threadIdx.x;
    const int r0 = blockIdx.x * 16;
    const int t = r0 >> 7, b0 = r0 & 127;
    for (int lin = tid; lin < 160; lin += 256) {
        int rr = lin / 10, k = lin % 10;
        s_dis2[rr][k] = g_dis[(size_t)(r0 + rr) * CONVW + k];
    }
    __syncthreads();
    for (int idx = tid; idx < 16 * HH; idx += 256) {
        int rr = idx / HH, i = idx - rr * HH;
        float acc = 0.f;
#pragma unroll
        for (int k = 0; k < CONVW; ++k) {
            int s = t - (CONVW - 1) + k;
            if (s >= 0)
                acc += s_dis2[rr][k] * g_h[((size_t)s * BB + b0 + rr) * HH + i];
        }
        s_mh[rr][i] = acc * (1.f / CONVW);
    }
    __syncthreads();
    for (int idx = tid; idx < 16 * HSS; idx += 256) {
        int rr = idx >> 6, j = idx & 63;
        float acc = bs[j];
        for (int i = 0; i < HH; ++i) acc += s_mh[rr][i] * Ws[i * HSS + j];
        s_q[rr][j] = fmaxf(acc, 0.f);
    }
    __syncthreads();
    for (int idx = tid; idx < 16 * HH; idx += 256) {
        int rr = idx / HH, o = idx - rr * HH;
        float acc = brs[o];
#pragma unroll 8
        for (int j = 0; j < HSS; ++j) acc += s_q[rr][j] * Wrs[j * HH + o];
        float theme = 1.f / (1.f + expf(-acc));
        int r = r0 + rr;
        int b = b0 + rr;
        out[((size_t)b * TT + t) * HH + o] =
            theme * g_conv[(size_t)r * HH + o] + g_h[((size_t)t * BB + b) * HH + o];
    }
}

// ---------------- entry ----------------
extern "C" void kernel_launch(void* const* d_in, const int* in_sizes, int n_in,
                              void* d_out, int out_size) {
    (void)in_sizes; (void)n_in; (void)out_size;
    const float* x   = (const float*)d_in[0];
    const float* Wk  = (const float*)d_in[2];
    const float* bk  = (const float*)d_in[3];
    const float* Wr  = (const float*)d_in[4];
    const float* br  = (const float*)d_in[5];
    const float* Ws  = (const float*)d_in[6];
    const float* bs  = (const float*)d_in[7];
    const float* Wrs = (const float*)d_in[8];
    const float* brs = (const float*)d_in[9];
    const float* Wc  = (const float*)d_in[10];
    const float* bc  = (const float*)d_in[11];
    float* out = (float*)d_out;

    k_prep_w<<<(int)(((size_t)NN * KK + 255) / 256), 256>>>(Wc);
    k1_xk<<<dim3(25, 1024), 256>>>(x, Wk, bk);
    k2_recurrent<<<136, 256>>>(Wr, br);
    k_dis<<<(NR + 255) / 256, 256>>>();
    k_split_h<<<(int)(((size_t)NR * HH / 4 + 255) / 256), 256>>>();
    k3_gemm<<<dim3(30, 512), 256>>>();
    k_gather<<<(int)(((size_t)NR * HH + 255) / 256), 256>>>(bc);
    k4_out<<<4096, 256>>>(Ws, bs, Wrs, brs, out);
}

// round 6
// speedup vs baseline: 1.9114x; 1.5691x over previous
#include <cuda_runtime.h>
#include <cuda_bf16.h>
#include <cstdint>
#include <math.h>

#define BB 128
#define TT 512
#define DD 128
#define HH 384
#define GG 1542
#define CONVW 10
#define HSS 64
#define NR (TT * BB)          /* 65536 rows */
#define NN 3840               /* K3 N = CONVW * HH */
#define KK 1152               /* K3 K = 3 * HH (bf16 split) */
#define K1K 384               /* K1 K = 3 * DD */
#define K1NP 1664             /* K1 N padded */
#define K2NP 1600             /* K2 N padded */

// ---------------- static device scratch ----------------
__device__ float g_xk[(size_t)NR * GG];
__device__ float g_xout[BB * GG];
__device__ float g_h[(size_t)NR * HH];
__device__ float g_c[BB * HH];
__device__ float g_dist[NR];
__device__ float g_dis[NR * CONVW];
__device__ float g_conv[(size_t)NR * HH];
__device__ float g_A[(size_t)NR * NN];
__device__ __nv_bfloat16 g_hhi[(size_t)NR * HH];
__device__ __nv_bfloat16 g_hlo[(size_t)NR * HH];
__device__ __nv_bfloat16 g_wbT[(size_t)NN * KK];      // K3 B
__device__ __nv_bfloat16 g_xhi[(size_t)NR * DD];
__device__ __nv_bfloat16 g_xlo[(size_t)NR * DD];
__device__ __nv_bfloat16 g_wkT[(size_t)K1NP * K1K];   // K1 B
__device__ __nv_bfloat16 g_wrhT[(size_t)K2NP * HH];   // K2 B hi
__device__ __nv_bfloat16 g_wrlT[(size_t)K2NP * HH];   // K2 B lo
__device__ volatile unsigned g_flags[128];
__device__ volatile unsigned g_relsd;

// ---------------- helpers ----------------
__device__ __forceinline__ uint32_t smem_u32(const void* p) {
    uint32_t a;
    asm("{ .reg .u64 t; cvta.to.shared.u64 t, %1; cvt.u32.u64 %0, t; }" : "=r"(a) : "l"(p));
    return a;
}
__device__ __forceinline__ void cp16(uint32_t s, const void* g) {
    asm volatile("cp.async.cg.shared.global [%0], [%1], 16;" :: "r"(s), "l"(g));
}

#define K2_NB 100

// flag-based grid barrier (replay-safe via monotonic release counter)
__device__ __forceinline__ void gbar(unsigned seq) {
    __threadfence();
    __syncthreads();
    if (blockIdx.x == 0) {
        if (threadIdx.x > 0 && threadIdx.x < K2_NB) {
            while (g_flags[threadIdx.x] < seq) { __nanosleep(40); }
        }
        __syncthreads();
        if (threadIdx.x == 0) g_relsd = seq;
        __syncthreads();
    } else {
        if (threadIdx.x == 0) {
            g_flags[blockIdx.x] = seq;
            while (g_relsd < seq) { __nanosleep(40); }
            __threadfence();
        }
        __syncthreads();
    }
}

// ---------------- prep kernels ----------------
__global__ void __launch_bounds__(256) k_split_x(const float* __restrict__ x) {
    size_t idx = (size_t)blockIdx.x * 256 + threadIdx.x;   // float4 index
    if (idx >= (size_t)NR * DD / 4) return;
    size_t e = idx * 4;
    int d4 = (int)(e & 127);
    int r = (int)(e >> 7);
    int t = r >> 7, b = r & 127;
    float4 v = *reinterpret_cast<const float4*>(x + ((size_t)b * TT + t) * DD + d4);
    __nv_bfloat16 h0 = __float2bfloat16(v.x), h1 = __float2bfloat16(v.y);
    __nv_bfloat16 h2 = __float2bfloat16(v.z), h3 = __float2bfloat16(v.w);
    __nv_bfloat162* hi = reinterpret_cast<__nv_bfloat162*>(g_xhi) + idx * 2;
    hi[0] = __nv_bfloat162(h0, h1); hi[1] = __nv_bfloat162(h2, h3);
    __nv_bfloat162* lo = reinterpret_cast<__nv_bfloat162*>(g_xlo) + idx * 2;
    lo[0] = __nv_bfloat162(__float2bfloat16(v.x - __bfloat162float(h0)),
                           __float2bfloat16(v.y - __bfloat162float(h1)));
    lo[1] = __nv_bfloat162(__float2bfloat16(v.z - __bfloat162float(h2)),
                           __float2bfloat16(v.w - __bfloat162float(h3)));
}

__global__ void __launch_bounds__(256) k_prep_wk(const float* __restrict__ Wk) {
    size_t idx = (size_t)blockIdx.x * 256 + threadIdx.x;
    if (idx >= (size_t)K1NP * K1K) return;
    int kc = (int)(idx % K1K);
    int n  = (int)(idx / K1K);
    int p = kc >> 7, i = kc & 127;
    float w = (n < GG) ? Wk[(size_t)i * GG + n] : 0.f;
    __nv_bfloat16 hi = __float2bfloat16(w);
    g_wkT[idx] = (p == 1) ? __float2bfloat16(w - __bfloat162float(hi)) : hi;
}

__global__ void __launch_bounds__(256) k_prep_wr(const float* __restrict__ Wr) {
    size_t idx = (size_t)blockIdx.x * 256 + threadIdx.x;
    if (idx >= (size_t)K2NP * HH) return;
    int k = (int)(idx % HH);
    int n = (int)(idx / HH);
    float w = (n < GG) ? Wr[(size_t)k * GG + n] : 0.f;
    __nv_bfloat16 hi = __float2bfloat16(w);
    g_wrhT[idx] = hi;
    g_wrlT[idx] = __float2bfloat16(w - __bfloat162float(hi));
}

__global__ void __launch_bounds__(256) k_prep_w(const float* __restrict__ Wc) {
    size_t idx = (size_t)blockIdx.x * 256 + threadIdx.x;
    if (idx >= (size_t)NN * KK) return;
    int kc = (int)(idx % KK);
    int n  = (int)(idx / KK);
    int p = kc / HH, i = kc - p * HH;
    int k = n / HH, o = n - k * HH;
    float w = Wc[((size_t)o * HH + i) * CONVW + k];
    __nv_bfloat16 hi = __float2bfloat16(w);
    g_wbT[idx] = (p == 1) ? __float2bfloat16(w - __bfloat162float(hi)) : hi;
}

// ---------------- K1 GEMM: g_xk = [x,1]@Wk + bk via HMMA ----------------
#define ROWB 80
__global__ void __launch_bounds__(256, 2) k1_gemm(const float* __restrict__ Wk,
                                                  const float* __restrict__ bk) {
    __shared__ __align__(128) char sbuf[2][2 * 128 * ROWB];
    const int tid = threadIdx.x;
    const int wid = tid >> 5;
    const int lane = tid & 31;
    const int wm = wid >> 2, wn = wid & 3;
    const int n0 = blockIdx.x * 128;
    const size_t r0 = (size_t)blockIdx.y * 128;
    const int grow = tid >> 1, ghalf = tid & 1;

    uint32_t sA[2], sB[2];
#pragma unroll
    for (int s = 0; s < 2; ++s) {
        sA[s] = smem_u32(&sbuf[s][0]);
        sB[s] = smem_u32(&sbuf[s][128 * ROWB]);
    }
    const int q4 = lane >> 3;
    const uint32_t aoff = (uint32_t)(((q4 & 1) * 8 + (lane & 7)) * ROWB + (q4 >> 1) * 16);
    const uint32_t boff = (uint32_t)((lane & 7) * ROWB + ((lane >> 3) & 1) * 16);

    auto issue = [&](int ch) {
        const int kb = ch * 32;
        const int p = kb >> 7;
        const int i0 = kb & 127;
        const __nv_bfloat16* src = (p == 2) ? g_xlo : g_xhi;
        const int buf = ch & 1;
        const __nv_bfloat16* ga = src + (r0 + grow) * DD + i0 + ghalf * 16;
        uint32_t da = sA[buf] + grow * ROWB + ghalf * 32;
        cp16(da, ga); cp16(da + 16, ga + 8);
        const __nv_bfloat16* gb = g_wkT + (size_t)(n0 + grow) * K1K + kb + ghalf * 16;
        uint32_t db = sB[buf] + grow * ROWB + ghalf * 32;
        cp16(db, gb); cp16(db + 16, gb + 8);
        asm volatile("cp.async.commit_group;");
    };
    issue(0); issue(1);
    float c[4][4][4] = {};
    const int NCH1 = K1K / 32;
    for (int ch = 0; ch < NCH1; ++ch) {
        if (ch == NCH1 - 1) asm volatile("cp.async.wait_group 0;");
        else                asm volatile("cp.async.wait_group 1;");
        __syncthreads();
        const int buf = ch & 1;
        const uint32_t abase = sA[buf] + (wm * 64) * ROWB + aoff;
        const uint32_t bbase = sB[buf] + (wn * 32) * ROWB + boff;
#pragma unroll
        for (int s = 0; s < 2; ++s) {
            uint32_t a[4][4];
#pragma unroll
            for (int i = 0; i < 4; ++i) {
                asm volatile("ldmatrix.sync.aligned.m8n8.x4.shared.b16 {%0,%1,%2,%3}, [%4];"
                             : "=r"(a[i][0]), "=r"(a[i][1]), "=r"(a[i][2]), "=r"(a[i][3])
                             : "r"(abase + i * 16 * ROWB + s * 32));
            }
            uint32_t bf[4][2];
#pragma unroll
            for (int j = 0; j < 4; ++j) {
                asm volatile("ldmatrix.sync.aligned.m8n8.x2.shared.b16 {%0,%1}, [%2];"
                             : "=r"(bf[j][0]), "=r"(bf[j][1])
                             : "r"(bbase + j * 8 * ROWB + s * 32));
            }
#pragma unroll
            for (int i = 0; i < 4; ++i)
#pragma unroll
                for (int j = 0; j < 4; ++j)
                    asm volatile(
                        "mma.sync.aligned.m16n8k16.row.col.f32.bf16.bf16.f32 "
                        "{%0,%1,%2,%3}, {%4,%5,%6,%7}, {%8,%9}, {%0,%1,%2,%3};"
                        : "+f"(c[i][j][0]), "+f"(c[i][j][1]), "+f"(c[i][j][2]), "+f"(c[i][j][3])
                        : "r"(a[i][0]), "r"(a[i][1]), "r"(a[i][2]), "r"(a[i][3]),
                          "r"(bf[j][0]), "r"(bf[j][1]));
        }
        __syncthreads();
        if (ch + 2 < NCH1) issue(ch + 2);
    }
    const int gq = lane >> 2, t4 = lane & 3;
#pragma unroll
    for (int i = 0; i < 4; ++i) {
        size_t row = r0 + wm * 64 + i * 16 + gq;
#pragma unroll
        for (int j = 0; j < 4; ++j) {
            int g = n0 + wn * 32 + j * 8 + t4 * 2;
            if (g < GG) {
                float b0v = Wk[(size_t)DD * GG + g] + bk[g];
                float b1v = Wk[(size_t)DD * GG + g + 1] + bk[g + 1];
                g_xk[row * GG + g]           = c[i][j][0] + b0v;
                g_xk[row * GG + g + 1]       = c[i][j][1] + b1v;
                g_xk[(row + 8) * GG + g]     = c[i][j][2] + b0v;
                g_xk[(row + 8) * GG + g + 1] = c[i][j][3] + b1v;
            }
        }
    }
}

// ---------------- K2: persistent HMMA recurrent scan ----------------
// 100 blocks = 4 m-tiles (32 b) x 25 n-tiles (64 g). Wr hi/lo cached in smem.
#define K2_PAD 784
#define K2_SM_WHI 0
#define K2_SM_WLO 50176
#define K2_SM_AHI 100352
#define K2_SM_ALO 125440
#define K2_SM_MST 150528
#define K2_SM_BIAS 152576
#define K2_SMEM 152832

__global__ void __launch_bounds__(256) k2_recurrent(const float* __restrict__ Wr,
                                                    const float* __restrict__ br) {
    extern __shared__ __align__(16) char s2[];
    const int tid = threadIdx.x;
    const int bid = blockIdx.x;
    const int mt = bid / 25, nt = bid % 25;
    const int b0 = mt * 32;
    const int n0 = nt * 64;
    const unsigned base = g_relsd;

    // persistent B load (hi/lo) + bias: 64 rows x 48 16B-chunks (= HH bf16)
    for (int q = tid; q < 64 * 48; q += 256) {
        int row = q / 48, cc = q % 48;
        *reinterpret_cast<uint4*>(s2 + K2_SM_WHI + row * K2_PAD + cc * 16) =
            *reinterpret_cast<const uint4*>(g_wrhT + (size_t)(n0 + row) * HH + cc * 8);
        *reinterpret_cast<uint4*>(s2 + K2_SM_WLO + row * K2_PAD + cc * 16) =
            *reinterpret_cast<const uint4*>(g_wrlT + (size_t)(n0 + row) * HH + cc * 8);
    }
    float* s_bias = reinterpret_cast<float*>(s2 + K2_SM_BIAS);
    for (int n = tid; n < 64; n += 256) {
        int g = n0 + n;
        s_bias[n] = (g < GG) ? (Wr[(size_t)HH * GG + g] + br[g]) : 0.f;
    }
    float* s_mst = reinterpret_cast<float*>(s2 + K2_SM_MST);
    for (int i = bid * 256 + tid; i < BB * HH; i += K2_NB * 256) g_c[i] = 0.f;
    unsigned seq = base + 1;
    gbar(seq);

    const int wid = tid >> 5, lane = tid & 31;
    const int wr = wid >> 2, wc = wid & 3;
    const int q4 = lane >> 3;
    const uint32_t fo = (uint32_t)(((q4 & 1) * 8 + (lane & 7)) * K2_PAD + (q4 >> 1) * 16);
    const uint32_t sbase = smem_u32(s2);
    const uint32_t a_hi = sbase + K2_SM_AHI + wr * 16 * K2_PAD + fo;
    const uint32_t a_lo = sbase + K2_SM_ALO + wr * 16 * K2_PAD + fo;
    const uint32_t b_hi = sbase + K2_SM_WHI + wc * 16 * K2_PAD + fo;
    const uint32_t b_lo = sbase + K2_SM_WLO + wc * 16 * K2_PAD + fo;
    const int gq = lane >> 2, t4 = lane & 3;

    for (int t = 0; t < TT; ++t) {
        float acc[2][4] = {};
        if (t > 0) {
            const size_t rb = (size_t)(t - 1) * BB + b0;
            // A tiles: 32 rows x 48 16B-chunks (hi and lo)
            for (int q = tid; q < 32 * 48; q += 256) {
                int row = q / 48, cc = q % 48;
                uint4 vh = __ldcg(reinterpret_cast<const uint4*>(
                    g_hhi + (rb + row) * HH + cc * 8));
                *reinterpret_cast<uint4*>(s2 + K2_SM_AHI + row * K2_PAD + cc * 16) = vh;
                uint4 vl = __ldcg(reinterpret_cast<const uint4*>(
                    g_hlo + (rb + row) * HH + cc * 8));
                *reinterpret_cast<uint4*>(s2 + K2_SM_ALO + row * K2_PAD + cc * 16) = vl;
            }
            __syncthreads();
#pragma unroll 1
            for (int pass = 0; pass < 3; ++pass) {
                const uint32_t ab = (pass == 2) ? a_lo : a_hi;
                const uint32_t bb = (pass == 1) ? b_lo : b_hi;
#pragma unroll
                for (int ki = 0; ki < 24; ++ki) {
                    uint32_t a[4], b[4];
                    asm volatile("ldmatrix.sync.aligned.m8n8.x4.shared.b16 {%0,%1,%2,%3}, [%4];"
                                 : "=r"(a[0]), "=r"(a[1]), "=r"(a[2]), "=r"(a[3])
                                 : "r"(ab + ki * 32));
                    asm volatile("ldmatrix.sync.aligned.m8n8.x4.shared.b16 {%0,%1,%2,%3}, [%4];"
                                 : "=r"(b[0]), "=r"(b[1]), "=r"(b[2]), "=r"(b[3])
                                 : "r"(bb + ki * 32));
                    asm volatile(
                        "mma.sync.aligned.m16n8k16.row.col.f32.bf16.bf16.f32 "
                        "{%0,%1,%2,%3}, {%4,%5,%6,%7}, {%8,%9}, {%0,%1,%2,%3};"
                        : "+f"(acc[0][0]), "+f"(acc[0][1]), "+f"(acc[0][2]), "+f"(acc[0][3])
                        : "r"(a[0]), "r"(a[1]), "r"(a[2]), "r"(a[3]),
                          "r"(b[0]), "r"(b[2]));
                    asm volatile(
                        "mma.sync.aligned.m16n8k16.row.col.f32.bf16.bf16.f32 "
                        "{%0,%1,%2,%3}, {%4,%5,%6,%7}, {%8,%9}, {%0,%1,%2,%3};"
                        : "+f"(acc[1][0]), "+f"(acc[1][1]), "+f"(acc[1][2]), "+f"(acc[1][3])
                        : "r"(a[0]), "r"(a[1]), "r"(a[2]), "r"(a[3]),
                          "r"(b[1]), "r"(b[3]));
                }
            }
        }
        // epilogue -> g_xout
        {
            const float* xkrow = g_xk + (size_t)t * BB * GG;
            int b1 = b0 + wr * 16 + gq;
            int b2 = b1 + 8;
#pragma unroll
            for (int j = 0; j < 2; ++j) {
                int col = wc * 16 + j * 8 + t4 * 2;
                int g = n0 + col;
                if (g < GG) {
                    float bi0 = s_bias[col], bi1 = s_bias[col + 1];
                    g_xout[b1 * GG + g]     = acc[j][0] + bi0 + __ldcg(&xkrow[(size_t)b1 * GG + g]);
                    g_xout[b1 * GG + g + 1] = acc[j][1] + bi1 + __ldcg(&xkrow[(size_t)b1 * GG + g + 1]);
                    g_xout[b2 * GG + g]     = acc[j][2] + bi0 + __ldcg(&xkrow[(size_t)b2 * GG + g]);
                    g_xout[b2 * GG + g + 1] = acc[j][3] + bi1 + __ldcg(&xkrow[(size_t)b2 * GG + g + 1]);
                }
            }
        }
        ++seq; gbar(seq);

        // masters (per batch row)
        if (tid < BB) {
            int b = tid;
            const float* row = g_xout + b * GG;
            float m0 = __ldcg(&row[0]), m1 = __ldcg(&row[1]), m2 = __ldcg(&row[2]);
            float v0 = __ldcg(&row[3]), v1 = __ldcg(&row[4]), v2 = __ldcg(&row[5]);
            float mx = fmaxf(m0, fmaxf(m1, m2));
            float e0 = expf(m0 - mx), e1 = expf(m1 - mx), e2 = expf(m2 - mx);
            float inv = 1.f / (e0 + e1 + e2);
            float f0 = e0 * inv, f1 = (e0 + e1) * inv;
            mx = fmaxf(v0, fmaxf(v1, v2));
            e0 = expf(v0 - mx); e1 = expf(v1 - mx); e2 = expf(v2 - mx);
            inv = 1.f / (e0 + e1 + e2);
            float i1v = (e1 + e2) * inv, i2v = e2 * inv;
            s_mst[b * 4 + 0] = f0;
            s_mst[b * 4 + 1] = f1;
            s_mst[b * 4 + 2] = i1v;
            s_mst[b * 4 + 3] = i2v;
            if (bid == 0) g_dist[t * BB + b] = 1.f - (f0 + f1 + 1.f) * (1.f / 3.f);
        }
        __syncthreads();
        for (int idx = bid * 256 + tid; idx < BB * HH; idx += K2_NB * 256) {
            int b = idx / HH, i = idx - b * HH;
            int l = i >> 7, c127 = i & 127;
            float fm = (l == 0) ? s_mst[b * 4] : ((l == 1) ? s_mst[b * 4 + 1] : 1.f);
            float im = (l == 0) ? 1.f : ((l == 1) ? s_mst[b * 4 + 2] : s_mst[b * 4 + 3]);
            float ov = fm * im;
            const float* row = g_xout + b * GG;
            float gf = __ldcg(&row[6 + l * 128 + c127]);
            float gi = __ldcg(&row[6 + (3 + l) * 128 + c127]);
            float go = __ldcg(&row[6 + (6 + l) * 128 + c127]);
            float gc = __ldcg(&row[6 + (9 + l) * 128 + c127]);
            float fg = 1.f / (1.f + expf(-gf));
            float ig = 1.f / (1.f + expf(-gi));
            float og = 1.f / (1.f + expf(-go));
            float ci = tanhf(gc);
            float cl = g_c[idx];
            float cn = (ov * fg + fm - ov) * cl + (ov * ig + im - ov) * ci;
            float hn = og * tanhf(cn);
            g_c[idx] = cn;
            size_t hx = (size_t)t * BB * HH + idx;
            g_h[hx] = hn;
            __nv_bfloat16 hh = __float2bfloat16(hn);
            g_hhi[hx] = hh;
            g_hlo[hx] = __float2bfloat16(hn - __bfloat162float(hh));
        }
        ++seq; gbar(seq);
    }
}

// ---------------- K_dis ----------------
__global__ void k_dis() {
    int idx = blockIdx.x * 256 + threadIdx.x;
    if (idx >= NR) return;
    int t = idx >> 7, b = idx & 127;
    float c[CONVW];
    float cum = 0.f;
#pragma unroll
    for (int k = 0; k < CONVW; ++k) {
        int s = t - (CONVW - 1) + k;
        float d = (s >= 0) ? g_dist[s * BB + b] : 0.f;
        cum += d;
        c[k] = cum;
    }
    float mx = c[0];
#pragma unroll
    for (int k = 1; k < CONVW; ++k) mx = fmaxf(mx, c[k]);
    float sum = 0.f;
#pragma unroll
    for (int k = 0; k < CONVW; ++k) { c[k] = expf(c[k] - mx); sum += c[k]; }
    float inv = 1.f / sum;
#pragma unroll
    for (int k = 0; k < CONVW; ++k) g_dis[(size_t)idx * CONVW + k] = c[k] * inv;
}

// ---------------- K3 GEMM ----------------
#define KSTEP 32
#define NCH (KK / KSTEP)
__global__ void __launch_bounds__(256, 2) k3_gemm() {
    __shared__ __align__(128) char sbuf[2][2 * 128 * ROWB];
    const int tid = threadIdx.x;
    const int wid = tid >> 5;
    const int lane = tid & 31;
    const int wm = wid >> 2, wn = wid & 3;
    const int n0 = blockIdx.x * 128;
    const size_t r0 = (size_t)blockIdx.y * 128;
    const int grow = tid >> 1, ghalf = tid & 1;
    uint32_t sA[2], sB[2];
#pragma unroll
    for (int s = 0; s < 2; ++s) {
        sA[s] = smem_u32(&sbuf[s][0]);
        sB[s] = smem_u32(&sbuf[s][128 * ROWB]);
    }
    const int q4 = lane >> 3;
    const uint32_t aoff = (uint32_t)(((q4 & 1) * 8 + (lane & 7)) * ROWB + (q4 >> 1) * 16);
    const uint32_t boff = (uint32_t)((lane & 7) * ROWB + ((lane >> 3) & 1) * 16);

    auto issue = [&](int ch) {
        const int kb = ch * KSTEP;
        const int p = kb / HH;
        const int i0 = kb - p * HH;
        const __nv_bfloat16* hsrc = (p == 2) ? g_hlo : g_hhi;
        const int buf = ch & 1;
        const __nv_bfloat16* ga = hsrc + (r0 + grow) * HH + i0 + ghalf * 16;
        uint32_t da = sA[buf] + grow * ROWB + ghalf * 32;
        cp16(da, ga); cp16(da + 16, ga + 8);
        const __nv_bfloat16* gb = g_wbT + (size_t)(n0 + grow) * KK + kb + ghalf * 16;
        uint32_t db = sB[buf] + grow * ROWB + ghalf * 32;
        cp16(db, gb); cp16(db + 16, gb + 8);
        asm volatile("cp.async.commit_group;");
    };
    issue(0); issue(1);
    float c[4][4][4] = {};
    for (int ch = 0; ch < NCH; ++ch) {
        if (ch == NCH - 1) asm volatile("cp.async.wait_group 0;");
        else               asm volatile("cp.async.wait_group 1;");
        __syncthreads();
        const int buf = ch & 1;
        const uint32_t abase = sA[buf] + (wm * 64) * ROWB + aoff;
        const uint32_t bbase = sB[buf] + (wn * 32) * ROWB + boff;
#pragma unroll
        for (int s = 0; s < 2; ++s) {
            uint32_t a[4][4];
#pragma unroll
            for (int i = 0; i < 4; ++i) {
                asm volatile("ldmatrix.sync.aligned.m8n8.x4.shared.b16 {%0,%1,%2,%3}, [%4];"
                             : "=r"(a[i][0]), "=r"(a[i][1]), "=r"(a[i][2]), "=r"(a[i][3])
                             : "r"(abase + i * 16 * ROWB + s * 32));
            }
            uint32_t bfr[4][2];
#pragma unroll
            for (int j = 0; j < 4; ++j) {
                asm volatile("ldmatrix.sync.aligned.m8n8.x2.shared.b16 {%0,%1}, [%2];"
                             : "=r"(bfr[j][0]), "=r"(bfr[j][1])
                             : "r"(bbase + j * 8 * ROWB + s * 32));
            }
#pragma unroll
            for (int i = 0; i < 4; ++i)
#pragma unroll
                for (int j = 0; j < 4; ++j)
                    asm volatile(
                        "mma.sync.aligned.m16n8k16.row.col.f32.bf16.bf16.f32 "
                        "{%0,%1,%2,%3}, {%4,%5,%6,%7}, {%8,%9}, {%0,%1,%2,%3};"
                        : "+f"(c[i][j][0]), "+f"(c[i][j][1]), "+f"(c[i][j][2]), "+f"(c[i][j][3])
                        : "r"(a[i][0]), "r"(a[i][1]), "r"(a[i][2]), "r"(a[i][3]),
                          "r"(bfr[j][0]), "r"(bfr[j][1]));
        }
        __syncthreads();
        if (ch + 2 < NCH) issue(ch + 2);
    }
    const int gq = lane >> 2, t4 = lane & 3;
#pragma unroll
    for (int i = 0; i < 4; ++i) {
        size_t row = r0 + wm * 64 + i * 16 + gq;
        float* dst0 = g_A + row * NN + n0 + wn * 32 + t4 * 2;
        float* dst1 = g_A + (row + 8) * NN + n0 + wn * 32 + t4 * 2;
#pragma unroll
        for (int j = 0; j < 4; ++j) {
            *reinterpret_cast<float2*>(dst0 + j * 8) = make_float2(c[i][j][0], c[i][j][1]);
            *reinterpret_cast<float2*>(dst1 + j * 8) = make_float2(c[i][j][2], c[i][j][3]);
        }
    }
}

// ---------------- gather ----------------
__global__ void __launch_bounds__(256) k_gather(const float* __restrict__ bc) {
    size_t idx = (size_t)blockIdx.x * 256 + threadIdx.x;
    if (idx >= (size_t)NR * HH) return;
    int o = (int)(idx % HH);
    int r = (int)(idx / HH);
    int t = r >> 7, b = r & 127;
    const float* dis = g_dis + (size_t)r * CONVW;
    float acc = bc[o];
    int kmin = (t >= CONVW - 1) ? 0 : (CONVW - 1 - t);
#pragma unroll
    for (int k = 0; k < CONVW; ++k) {
        if (k >= kmin) {
            int s = t - (CONVW - 1) + k;
            acc += dis[k] * g_A[((size_t)s * BB + b) * NN + (size_t)k * HH + o];
        }
    }
    g_conv[(size_t)r * HH + o] = acc;
}

// ---------------- K4 ----------------
__global__ void __launch_bounds__(256) k4_out(const float* __restrict__ Ws,
                                              const float* __restrict__ bs,
                                              const float* __restrict__ Wrs,
                                              const float* __restrict__ brs,
                                              float* __restrict__ out) {
    __shared__ float s_mh[16][HH];
    __shared__ float s_q[16][HSS];
    __shared__ float s_dis2[16][10];
    const int tid = threadIdx.x;
    const int r0 = blockIdx.x * 16;
    const int t = r0 >> 7, b0 = r0 & 127;
    for (int lin = tid; lin < 160; lin += 256) {
        int rr = lin / 10, k = lin % 10;
        s_dis2[rr][k] = g_dis[(size_t)(r0 + rr) * CONVW + k];
    }
    __syncthreads();
    for (int idx = tid; idx < 16 * HH; idx += 256) {
        int rr = idx / HH, i = idx - rr * HH;
        float acc = 0.f;
#pragma unroll
        for (int k = 0; k < CONVW; ++k) {
            int s = t - (CONVW - 1) + k;
            if (s >= 0)
                acc += s_dis2[rr][k] * g_h[((size_t)s * BB + b0 + rr) * HH + i];
        }
        s_mh[rr][i] = acc * (1.f / CONVW);
    }
    __syncthreads();
    for (int idx = tid; idx < 16 * HSS; idx += 256) {
        int rr = idx >> 6, j = idx & 63;
        float acc = bs[j];
        for (int i = 0; i < HH; ++i) acc += s_mh[rr][i] * Ws[i * HSS + j];
        s_q[rr][j] = fmaxf(acc, 0.f);
    }
    __syncthreads();
    for (int idx = tid; idx < 16 * HH; idx += 256) {
        int rr = idx / HH, o = idx - rr * HH;
        float acc = brs[o];
#pragma unroll 8
        for (int j = 0; j < HSS; ++j) acc += s_q[rr][j] * Wrs[j * HH + o];
        float theme = 1.f / (1.f + expf(-acc));
        int r = r0 + rr;
        int b = b0 + rr;
        out[((size_t)b * TT + t) * HH + o] =
            theme * g_conv[(size_t)r * HH + o] + g_h[((size_t)t * BB + b) * HH + o];
    }
}

// ---------------- entry ----------------
extern "C" void kernel_launch(void* const* d_in, const int* in_sizes, int n_in,
                              void* d_out, int out_size) {
    (void)in_sizes; (void)n_in; (void)out_size;
    const float* x   = (const float*)d_in[0];
    const float* Wk  = (const float*)d_in[2];
    const float* bk  = (const float*)d_in[3];
    const float* Wr  = (const float*)d_in[4];
    const float* br  = (const float*)d_in[5];
    const float* Ws  = (const float*)d_in[6];
    const float* bs  = (const float*)d_in[7];
    const float* Wrs = (const float*)d_in[8];
    const float* brs = (const float*)d_in[9];
    const float* Wc  = (const float*)d_in[10];
    const float* bc  = (const float*)d_in[11];
    float* out = (float*)d_out;

    cudaFuncSetAttribute(k2_recurrent, cudaFuncAttributeMaxDynamicSharedMemorySize, K2_SMEM);

    k_prep_w<<<(int)(((size_t)NN * KK + 255) / 256), 256>>>(Wc);
    k_prep_wk<<<(int)(((size_t)K1NP * K1K + 255) / 256), 256>>>(Wk);
    k_prep_wr<<<(int)(((size_t)K2NP * HH + 255) / 256), 256>>>(Wr);
    k_split_x<<<(int)(((size_t)NR * DD / 4 + 255) / 256), 256>>>(x);
    k1_gemm<<<dim3(13, 512), 256>>>(Wk, bk);
    k2_recurrent<<<K2_NB, 256, K2_SMEM>>>(Wr, br);
    k_dis<<<(NR + 255) / 256, 256>>>();
    k3_gemm<<<dim3(30, 512), 256>>>();
    k_gather<<<(int)(((size_t)NR * HH + 255) / 256), 256>>>(bc);
    k4_out<<<4096, 256>>>(Ws, bs, Wrs, brs, out);
}

// round 7
// speedup vs baseline: 2.3608x; 1.2351x over previous
#include <cuda_runtime.h>
#include <cuda_bf16.h>
#include <cuda_fp16.h>
#include <cstdint>
#include <math.h>

#define BB 128
#define TT 512
#define DD 128
#define HH 384
#define GG 1542
#define CONVW 10
#define HSS 64
#define NR (TT * BB)          /* 65536 rows */
#define NN 3840               /* K3 N = CONVW * HH */
#define K3K 384               /* K3 K (fp16 single pass) */
#define K1K 128               /* K1 K (fp16 single pass) */
#define K1NP 1664             /* K1 N padded */
#define K2NP 1600             /* K2 N padded */

// ---------------- static device scratch ----------------
__device__ float g_xk[(size_t)NR * GG];
__device__ float g_xout[BB * GG];
__device__ float g_h[(size_t)NR * HH];
__device__ float g_c[BB * HH];
__device__ float g_dist[NR];
__device__ float g_dis[NR * CONVW];
__device__ float g_conv[(size_t)NR * HH];
__device__ float g_A[(size_t)NR * NN];
__device__ __nv_bfloat16 g_hhi[(size_t)NR * HH];   // K2 A hi
__device__ __nv_bfloat16 g_hlo[(size_t)NR * HH];   // K2 A lo
__device__ __half g_hf[(size_t)NR * HH];           // K3 A (fp16)
__device__ __half g_wbh[(size_t)NN * K3K];         // K3 B (fp16)
__device__ __half g_xh[(size_t)NR * DD];           // K1 A (fp16)
__device__ __half g_wkh[(size_t)K1NP * K1K];       // K1 B (fp16)
__device__ __nv_bfloat16 g_wrhT[(size_t)K2NP * HH];   // K2 B hi
__device__ __nv_bfloat16 g_wrlT[(size_t)K2NP * HH];   // K2 B lo
__device__ volatile unsigned g_flags[128];
__device__ volatile unsigned g_relsd;

// ---------------- helpers ----------------
__device__ __forceinline__ uint32_t smem_u32(const void* p) {
    uint32_t a;
    asm("{ .reg .u64 t; cvta.to.shared.u64 t, %1; cvt.u32.u64 %0, t; }" : "=r"(a) : "l"(p));
    return a;
}
__device__ __forceinline__ void cp16(uint32_t s, const void* g) {
    asm volatile("cp.async.cg.shared.global [%0], [%1], 16;" :: "r"(s), "l"(g));
}

#define K2_NB 100

// flag-based grid barrier (replay-safe via monotonic release counter)
__device__ __forceinline__ void gbar(unsigned seq) {
    __threadfence();
    __syncthreads();
    if (blockIdx.x == 0) {
        if (threadIdx.x > 0 && threadIdx.x < K2_NB) {
            while (g_flags[threadIdx.x] < seq) { __nanosleep(40); }
        }
        __syncthreads();
        if (threadIdx.x == 0) g_relsd = seq;
        __syncthreads();
    } else {
        if (threadIdx.x == 0) {
            g_flags[blockIdx.x] = seq;
            while (g_relsd < seq) { __nanosleep(40); }
            __threadfence();
        }
        __syncthreads();
    }
}

// ---------------- prep kernels ----------------
__global__ void __launch_bounds__(256) k_half_x(const float* __restrict__ x) {
    size_t idx = (size_t)blockIdx.x * 256 + threadIdx.x;   // float4 index
    if (idx >= (size_t)NR * DD / 4) return;
    size_t e = idx * 4;
    int d4 = (int)(e & 127);
    int r = (int)(e >> 7);
    int t = r >> 7, b = r & 127;
    float4 v = *reinterpret_cast<const float4*>(x + ((size_t)b * TT + t) * DD + d4);
    __half2* dst = reinterpret_cast<__half2*>(g_xh) + idx * 2;
    dst[0] = __floats2half2_rn(v.x, v.y);
    dst[1] = __floats2half2_rn(v.z, v.w);
}

__global__ void __launch_bounds__(256) k_prep_wk(const float* __restrict__ Wk) {
    size_t idx = (size_t)blockIdx.x * 256 + threadIdx.x;
    if (idx >= (size_t)K1NP * K1K) return;
    int i = (int)(idx % K1K);
    int n = (int)(idx / K1K);
    float w = (n < GG) ? Wk[(size_t)i * GG + n] : 0.f;
    g_wkh[idx] = __float2half(w);
}

__global__ void __launch_bounds__(256) k_prep_wr(const float* __restrict__ Wr) {
    size_t idx = (size_t)blockIdx.x * 256 + threadIdx.x;
    if (idx >= (size_t)K2NP * HH) return;
    int k = (int)(idx % HH);
    int n = (int)(idx / HH);
    float w = (n < GG) ? Wr[(size_t)k * GG + n] : 0.f;
    __nv_bfloat16 hi = __float2bfloat16(w);
    g_wrhT[idx] = hi;
    g_wrlT[idx] = __float2bfloat16(w - __bfloat162float(hi));
}

__global__ void __launch_bounds__(256) k_prep_w(const float* __restrict__ Wc) {
    size_t idx = (size_t)blockIdx.x * 256 + threadIdx.x;
    if (idx >= (size_t)NN * K3K) return;
    int i = (int)(idx % K3K);
    int n = (int)(idx / K3K);
    int k = n / HH, o = n - k * HH;
    g_wbh[idx] = __float2half(Wc[((size_t)o * HH + i) * CONVW + k]);
}

// ---------------- K1 GEMM: g_xk = [x,1]@Wk + bk via fp16 HMMA ----------------
#define ROWB 80
__global__ void __launch_bounds__(256, 2) k1_gemm(const float* __restrict__ Wk,
                                                  const float* __restrict__ bk) {
    __shared__ __align__(128) char sbuf[2][2 * 128 * ROWB];
    const int tid = threadIdx.x;
    const int wid = tid >> 5;
    const int lane = tid & 31;
    const int wm = wid >> 2, wn = wid & 3;
    const int n0 = blockIdx.x * 128;
    const size_t r0 = (size_t)blockIdx.y * 128;
    const int grow = tid >> 1, ghalf = tid & 1;

    uint32_t sA[2], sB[2];
#pragma unroll
    for (int s = 0; s < 2; ++s) {
        sA[s] = smem_u32(&sbuf[s][0]);
        sB[s] = smem_u32(&sbuf[s][128 * ROWB]);
    }
    const int q4 = lane >> 3;
    const uint32_t aoff = (uint32_t)(((q4 & 1) * 8 + (lane & 7)) * ROWB + (q4 >> 1) * 16);
    const uint32_t boff = (uint32_t)((lane & 7) * ROWB + ((lane >> 3) & 1) * 16);

    auto issue = [&](int ch) {
        const int kb = ch * 32;
        const int buf = ch & 1;
        const __half* ga = g_xh + (r0 + grow) * DD + kb + ghalf * 16;
        uint32_t da = sA[buf] + grow * ROWB + ghalf * 32;
        cp16(da, ga); cp16(da + 16, ga + 8);
        const __half* gb = g_wkh + (size_t)(n0 + grow) * K1K + kb + ghalf * 16;
        uint32_t db = sB[buf] + grow * ROWB + ghalf * 32;
        cp16(db, gb); cp16(db + 16, gb + 8);
        asm volatile("cp.async.commit_group;");
    };
    issue(0); issue(1);
    float c[4][4][4] = {};
    const int NCH1 = K1K / 32;   // 4
    for (int ch = 0; ch < NCH1; ++ch) {
        if (ch == NCH1 - 1) asm volatile("cp.async.wait_group 0;");
        else                asm volatile("cp.async.wait_group 1;");
        __syncthreads();
        const int buf = ch & 1;
        const uint32_t abase = sA[buf] + (wm * 64) * ROWB + aoff;
        const uint32_t bbase = sB[buf] + (wn * 32) * ROWB + boff;
#pragma unroll
        for (int s = 0; s < 2; ++s) {
            uint32_t a[4][4];
#pragma unroll
            for (int i = 0; i < 4; ++i) {
                asm volatile("ldmatrix.sync.aligned.m8n8.x4.shared.b16 {%0,%1,%2,%3}, [%4];"
                             : "=r"(a[i][0]), "=r"(a[i][1]), "=r"(a[i][2]), "=r"(a[i][3])
                             : "r"(abase + i * 16 * ROWB + s * 32));
            }
            uint32_t bf[4][2];
#pragma unroll
            for (int j = 0; j < 4; ++j) {
                asm volatile("ldmatrix.sync.aligned.m8n8.x2.shared.b16 {%0,%1}, [%2];"
                             : "=r"(bf[j][0]), "=r"(bf[j][1])
                             : "r"(bbase + j * 8 * ROWB + s * 32));
            }
#pragma unroll
            for (int i = 0; i < 4; ++i)
#pragma unroll
                for (int j = 0; j < 4; ++j)
                    asm volatile(
                        "mma.sync.aligned.m16n8k16.row.col.f32.f16.f16.f32 "
                        "{%0,%1,%2,%3}, {%4,%5,%6,%7}, {%8,%9}, {%0,%1,%2,%3};"
                        : "+f"(c[i][j][0]), "+f"(c[i][j][1]), "+f"(c[i][j][2]), "+f"(c[i][j][3])
                        : "r"(a[i][0]), "r"(a[i][1]), "r"(a[i][2]), "r"(a[i][3]),
                          "r"(bf[j][0]), "r"(bf[j][1]));
        }
        __syncthreads();
        if (ch + 2 < NCH1) issue(ch + 2);
    }
    const int gq = lane >> 2, t4 = lane & 3;
#pragma unroll
    for (int i = 0; i < 4; ++i) {
        size_t row = r0 + wm * 64 + i * 16 + gq;
#pragma unroll
        for (int j = 0; j < 4; ++j) {
            int g = n0 + wn * 32 + j * 8 + t4 * 2;
            if (g < GG) {
                float b0v = Wk[(size_t)DD * GG + g] + bk[g];
                float b1v = Wk[(size_t)DD * GG + g + 1] + bk[g + 1];
                g_xk[row * GG + g]           = c[i][j][0] + b0v;
                g_xk[row * GG + g + 1]       = c[i][j][1] + b1v;
                g_xk[(row + 8) * GG + g]     = c[i][j][2] + b0v;
                g_xk[(row + 8) * GG + g + 1] = c[i][j][3] + b1v;
            }
        }
    }
}

// ---------------- K2: persistent HMMA recurrent scan (bf16 3-pass) ----------------
#define K2_PAD 784
#define K2_SM_WHI 0
#define K2_SM_WLO 50176
#define K2_SM_AHI 100352
#define K2_SM_ALO 125440
#define K2_SM_MST 150528
#define K2_SM_BIAS 152576
#define K2_SMEM 152832

__global__ void __launch_bounds__(256) k2_recurrent(const float* __restrict__ Wr,
                                                    const float* __restrict__ br) {
    extern __shared__ __align__(16) char s2[];
    const int tid = threadIdx.x;
    const int bid = blockIdx.x;
    const int mt = bid / 25, nt = bid % 25;
    const int b0 = mt * 32;
    const int n0 = nt * 64;
    const unsigned base = g_relsd;

    for (int q = tid; q < 64 * 48; q += 256) {
        int row = q / 48, cc = q % 48;
        *reinterpret_cast<uint4*>(s2 + K2_SM_WHI + row * K2_PAD + cc * 16) =
            *reinterpret_cast<const uint4*>(g_wrhT + (size_t)(n0 + row) * HH + cc * 8);
        *reinterpret_cast<uint4*>(s2 + K2_SM_WLO + row * K2_PAD + cc * 16) =
            *reinterpret_cast<const uint4*>(g_wrlT + (size_t)(n0 + row) * HH + cc * 8);
    }
    float* s_bias = reinterpret_cast<float*>(s2 + K2_SM_BIAS);
    for (int n = tid; n < 64; n += 256) {
        int g = n0 + n;
        s_bias[n] = (g < GG) ? (Wr[(size_t)HH * GG + g] + br[g]) : 0.f;
    }
    float* s_mst = reinterpret_cast<float*>(s2 + K2_SM_MST);
    for (int i = bid * 256 + tid; i < BB * HH; i += K2_NB * 256) g_c[i] = 0.f;
    unsigned seq = base + 1;
    gbar(seq);

    const int wid = tid >> 5, lane = tid & 31;
    const int wr = wid >> 2, wc = wid & 3;
    const int q4 = lane >> 3;
    const uint32_t fo = (uint32_t)(((q4 & 1) * 8 + (lane & 7)) * K2_PAD + (q4 >> 1) * 16);
    const uint32_t sbase = smem_u32(s2);
    const uint32_t a_hi = sbase + K2_SM_AHI + wr * 16 * K2_PAD + fo;
    const uint32_t a_lo = sbase + K2_SM_ALO + wr * 16 * K2_PAD + fo;
    const uint32_t b_hi = sbase + K2_SM_WHI + wc * 16 * K2_PAD + fo;
    const uint32_t b_lo = sbase + K2_SM_WLO + wc * 16 * K2_PAD + fo;
    const int gq = lane >> 2, t4 = lane & 3;

    for (int t = 0; t < TT; ++t) {
        float acc[2][4] = {};
        if (t > 0) {
            const size_t rb = (size_t)(t - 1) * BB + b0;
            for (int q = tid; q < 32 * 48; q += 256) {
                int row = q / 48, cc = q % 48;
                uint4 vh = __ldcg(reinterpret_cast<const uint4*>(
                    g_hhi + (rb + row) * HH + cc * 8));
                *reinterpret_cast<uint4*>(s2 + K2_SM_AHI + row * K2_PAD + cc * 16) = vh;
                uint4 vl = __ldcg(reinterpret_cast<const uint4*>(
                    g_hlo + (rb + row) * HH + cc * 8));
                *reinterpret_cast<uint4*>(s2 + K2_SM_ALO + row * K2_PAD + cc * 16) = vl;
            }
            __syncthreads();
#pragma unroll 1
            for (int pass = 0; pass < 3; ++pass) {
                const uint32_t ab = (pass == 2) ? a_lo : a_hi;
                const uint32_t bb = (pass == 1) ? b_lo : b_hi;
#pragma unroll
                for (int ki = 0; ki < 24; ++ki) {
                    uint32_t a[4], b[4];
                    asm volatile("ldmatrix.sync.aligned.m8n8.x4.shared.b16 {%0,%1,%2,%3}, [%4];"
                                 : "=r"(a[0]), "=r"(a[1]), "=r"(a[2]), "=r"(a[3])
                                 : "r"(ab + ki * 32));
                    asm volatile("ldmatrix.sync.aligned.m8n8.x4.shared.b16 {%0,%1,%2,%3}, [%4];"
                                 : "=r"(b[0]), "=r"(b[1]), "=r"(b[2]), "=r"(b[3])
                                 : "r"(bb + ki * 32));
                    asm volatile(
                        "mma.sync.aligned.m16n8k16.row.col.f32.bf16.bf16.f32 "
                        "{%0,%1,%2,%3}, {%4,%5,%6,%7}, {%8,%9}, {%0,%1,%2,%3};"
                        : "+f"(acc[0][0]), "+f"(acc[0][1]), "+f"(acc[0][2]), "+f"(acc[0][3])
                        : "r"(a[0]), "r"(a[1]), "r"(a[2]), "r"(a[3]),
                          "r"(b[0]), "r"(b[2]));
                    asm volatile(
                        "mma.sync.aligned.m16n8k16.row.col.f32.bf16.bf16.f32 "
                        "{%0,%1,%2,%3}, {%4,%5,%6,%7}, {%8,%9}, {%0,%1,%2,%3};"
                        : "+f"(acc[1][0]), "+f"(acc[1][1]), "+f"(acc[1][2]), "+f"(acc[1][3])
                        : "r"(a[0]), "r"(a[1]), "r"(a[2]), "r"(a[3]),
                          "r"(b[1]), "r"(b[3]));
                }
            }
        }
        // epilogue -> g_xout
        {
            const float* xkrow = g_xk + (size_t)t * BB * GG;
            int b1 = b0 + wr * 16 + gq;
            int b2 = b1 + 8;
#pragma unroll
            for (int j = 0; j < 2; ++j) {
                int col = wc * 16 + j * 8 + t4 * 2;
                int g = n0 + col;
                if (g < GG) {
                    float bi0 = s_bias[col], bi1 = s_bias[col + 1];
                    g_xout[b1 * GG + g]     = acc[j][0] + bi0 + __ldcg(&xkrow[(size_t)b1 * GG + g]);
                    g_xout[b1 * GG + g + 1] = acc[j][1] + bi1 + __ldcg(&xkrow[(size_t)b1 * GG + g + 1]);
                    g_xout[b2 * GG + g]     = acc[j][2] + bi0 + __ldcg(&xkrow[(size_t)b2 * GG + g]);
                    g_xout[b2 * GG + g + 1] = acc[j][3] + bi1 + __ldcg(&xkrow[(size_t)b2 * GG + g + 1]);
                }
            }
        }
        ++seq; gbar(seq);

        // masters (per batch row)
        if (tid < BB) {
            int b = tid;
            const float* row = g_xout + b * GG;
            float m0 = __ldcg(&row[0]), m1 = __ldcg(&row[1]), m2 = __ldcg(&row[2]);
            float v0 = __ldcg(&row[3]), v1 = __ldcg(&row[4]), v2 = __ldcg(&row[5]);
            float mx = fmaxf(m0, fmaxf(m1, m2));
            float e0 = expf(m0 - mx), e1 = expf(m1 - mx), e2 = expf(m2 - mx);
            float inv = 1.f / (e0 + e1 + e2);
            float f0 = e0 * inv, f1 = (e0 + e1) * inv;
            mx = fmaxf(v0, fmaxf(v1, v2));
            e0 = expf(v0 - mx); e1 = expf(v1 - mx); e2 = expf(v2 - mx);
            inv = 1.f / (e0 + e1 + e2);
            float i1v = (e1 + e2) * inv, i2v = e2 * inv;
            s_mst[b * 4 + 0] = f0;
            s_mst[b * 4 + 1] = f1;
            s_mst[b * 4 + 2] = i1v;
            s_mst[b * 4 + 3] = i2v;
            if (bid == 0) g_dist[t * BB + b] = 1.f - (f0 + f1 + 1.f) * (1.f / 3.f);
        }
        __syncthreads();
        for (int idx = bid * 256 + tid; idx < BB * HH; idx += K2_NB * 256) {
            int b = idx / HH, i = idx - b * HH;
            int l = i >> 7, c127 = i & 127;
            float fm = (l == 0) ? s_mst[b * 4] : ((l == 1) ? s_mst[b * 4 + 1] : 1.f);
            float im = (l == 0) ? 1.f : ((l == 1) ? s_mst[b * 4 + 2] : s_mst[b * 4 + 3]);
            float ov = fm * im;
            const float* row = g_xout + b * GG;
            float gf = __ldcg(&row[6 + l * 128 + c127]);
            float gi = __ldcg(&row[6 + (3 + l) * 128 + c127]);
            float go = __ldcg(&row[6 + (6 + l) * 128 + c127]);
            float gc = __ldcg(&row[6 + (9 + l) * 128 + c127]);
            float fg = 1.f / (1.f + expf(-gf));
            float ig = 1.f / (1.f + expf(-gi));
            float og = 1.f / (1.f + expf(-go));
            float ci = tanhf(gc);
            float cl = g_c[idx];
            float cn = (ov * fg + fm - ov) * cl + (ov * ig + im - ov) * ci;
            float hn = og * tanhf(cn);
            g_c[idx] = cn;
            size_t hx = (size_t)t * BB * HH + idx;
            g_h[hx] = hn;
            __nv_bfloat16 hh = __float2bfloat16(hn);
            g_hhi[hx] = hh;
            g_hlo[hx] = __float2bfloat16(hn - __bfloat162float(hh));
            g_hf[hx] = __float2half(hn);
        }
        ++seq; gbar(seq);
    }
}

// ---------------- K_dis ----------------
__global__ void k_dis() {
    int idx = blockIdx.x * 256 + threadIdx.x;
    if (idx >= NR) return;
    int t = idx >> 7, b = idx & 127;
    float c[CONVW];
    float cum = 0.f;
#pragma unroll
    for (int k = 0; k < CONVW; ++k) {
        int s = t - (CONVW - 1) + k;
        float d = (s >= 0) ? g_dist[s * BB + b] : 0.f;
        cum += d;
        c[k] = cum;
    }
    float mx = c[0];
#pragma unroll
    for (int k = 1; k < CONVW; ++k) mx = fmaxf(mx, c[k]);
    float sum = 0.f;
#pragma unroll
    for (int k = 0; k < CONVW; ++k) { c[k] = expf(c[k] - mx); sum += c[k]; }
    float inv = 1.f / sum;
#pragma unroll
    for (int k = 0; k < CONVW; ++k) g_dis[(size_t)idx * CONVW + k] = c[k] * inv;
}

// ---------------- K3 GEMM (fp16 single pass, K=384) ----------------
#define KSTEP 32
#define NCH3 (K3K / KSTEP)    /* 12 */
__global__ void __launch_bounds__(256, 2) k3_gemm() {
    __shared__ __align__(128) char sbuf[2][2 * 128 * ROWB];
    const int tid = threadIdx.x;
    const int wid = tid >> 5;
    const int lane = tid & 31;
    const int wm = wid >> 2, wn = wid & 3;
    const int n0 = blockIdx.x * 128;
    const size_t r0 = (size_t)blockIdx.y * 128;
    const int grow = tid >> 1, ghalf = tid & 1;
    uint32_t sA[2], sB[2];
#pragma unroll
    for (int s = 0; s < 2; ++s) {
        sA[s] = smem_u32(&sbuf[s][0]);
        sB[s] = smem_u32(&sbuf[s][128 * ROWB]);
    }
    const int q4 = lane >> 3;
    const uint32_t aoff = (uint32_t)(((q4 & 1) * 8 + (lane & 7)) * ROWB + (q4 >> 1) * 16);
    const uint32_t boff = (uint32_t)((lane & 7) * ROWB + ((lane >> 3) & 1) * 16);

    auto issue = [&](int ch) {
        const int kb = ch * KSTEP;
        const int buf = ch & 1;
        const __half* ga = g_hf + (r0 + grow) * HH + kb + ghalf * 16;
        uint32_t da = sA[buf] + grow * ROWB + ghalf * 32;
        cp16(da, ga); cp16(da + 16, ga + 8);
        const __half* gb = g_wbh + (size_t)(n0 + grow) * K3K + kb + ghalf * 16;
        uint32_t db = sB[buf] + grow * ROWB + ghalf * 32;
        cp16(db, gb); cp16(db + 16, gb + 8);
        asm volatile("cp.async.commit_group;");
    };
    issue(0); issue(1);
    float c[4][4][4] = {};
    for (int ch = 0; ch < NCH3; ++ch) {
        if (ch == NCH3 - 1) asm volatile("cp.async.wait_group 0;");
        else                asm volatile("cp.async.wait_group 1;");
        __syncthreads();
        const int buf = ch & 1;
        const uint32_t abase = sA[buf] + (wm * 64) * ROWB + aoff;
        const uint32_t bbase = sB[buf] + (wn * 32) * ROWB + boff;
#pragma unroll
        for (int s = 0; s < 2; ++s) {
            uint32_t a[4][4];
#pragma unroll
            for (int i = 0; i < 4; ++i) {
                asm volatile("ldmatrix.sync.aligned.m8n8.x4.shared.b16 {%0,%1,%2,%3}, [%4];"
                             : "=r"(a[i][0]), "=r"(a[i][1]), "=r"(a[i][2]), "=r"(a[i][3])
                             : "r"(abase + i * 16 * ROWB + s * 32));
            }
            uint32_t bfr[4][2];
#pragma unroll
            for (int j = 0; j < 4; ++j) {
                asm volatile("ldmatrix.sync.aligned.m8n8.x2.shared.b16 {%0,%1}, [%2];"
                             : "=r"(bfr[j][0]), "=r"(bfr[j][1])
                             : "r"(bbase + j * 8 * ROWB + s * 32));
            }
#pragma unroll
            for (int i = 0; i < 4; ++i)
#pragma unroll
                for (int j = 0; j < 4; ++j)
                    asm volatile(
                        "mma.sync.aligned.m16n8k16.row.col.f32.f16.f16.f32 "
                        "{%0,%1,%2,%3}, {%4,%5,%6,%7}, {%8,%9}, {%0,%1,%2,%3};"
                        : "+f"(c[i][j][0]), "+f"(c[i][j][1]), "+f"(c[i][j][2]), "+f"(c[i][j][3])
                        : "r"(a[i][0]), "r"(a[i][1]), "r"(a[i][2]), "r"(a[i][3]),
                          "r"(bfr[j][0]), "r"(bfr[j][1]));
        }
        __syncthreads();
        if (ch + 2 < NCH3) issue(ch + 2);
    }
    const int gq = lane >> 2, t4 = lane & 3;
#pragma unroll
    for (int i = 0; i < 4; ++i) {
        size_t row = r0 + wm * 64 + i * 16 + gq;
        float* dst0 = g_A + row * NN + n0 + wn * 32 + t4 * 2;
        float* dst1 = g_A + (row + 8) * NN + n0 + wn * 32 + t4 * 2;
#pragma unroll
        for (int j = 0; j < 4; ++j) {
            *reinterpret_cast<float2*>(dst0 + j * 8) = make_float2(c[i][j][0], c[i][j][1]);
            *reinterpret_cast<float2*>(dst1 + j * 8) = make_float2(c[i][j][2], c[i][j][3]);
        }
    }
}

// ---------------- gather ----------------
__global__ void __launch_bounds__(256) k_gather(const float* __restrict__ bc) {
    size_t idx = (size_t)blockIdx.x * 256 + threadIdx.x;
    if (idx >= (size_t)NR * HH) return;
    int o = (int)(idx % HH);
    int r = (int)(idx / HH);
    int t = r >> 7, b = r & 127;
    const float* dis = g_dis + (size_t)r * CONVW;
    float acc = bc[o];
    int kmin = (t >= CONVW - 1) ? 0 : (CONVW - 1 - t);
#pragma unroll
    for (int k = 0; k < CONVW; ++k) {
        if (k >= kmin) {
            int s = t - (CONVW - 1) + k;
            acc += dis[k] * g_A[((size_t)s * BB + b) * NN + (size_t)k * HH + o];
        }
    }
    g_conv[(size_t)r * HH + o] = acc;
}

// ---------------- K4 ----------------
__global__ void __launch_bounds__(256) k4_out(const float* __restrict__ Ws,
                                              const float* __restrict__ bs,
                                              const float* __restrict__ Wrs,
                                              const float* __restrict__ brs,
                                              float* __restrict__ out) {
    __shared__ float s_mh[16][HH];
    __shared__ float s_q[16][HSS];
    __shared__ float s_dis2[16][10];
    const int tid = threadIdx.x;
    const int r0 = blockIdx.x * 16;
    const int t = r0 >> 7, b0 = r0 & 127;
    for (int lin = tid; lin < 160; lin += 256) {
        int rr = lin / 10, k = lin % 10;
        s_dis2[rr][k] = g_dis[(size_t)(r0 + rr) * CONVW + k];
    }
    __syncthreads();
    for (int idx = tid; idx < 16 * HH; idx += 256) {
        int rr = idx / HH, i = idx - rr * HH;
        float acc = 0.f;
#pragma unroll
        for (int k = 0; k < CONVW; ++k) {
            int s = t - (CONVW - 1) + k;
            if (s >= 0)
                acc += s_dis2[rr][k] * g_h[((size_t)s * BB + b0 + rr) * HH + i];
        }
        s_mh[rr][i] = acc * (1.f / CONVW);
    }
    __syncthreads();
    for (int idx = tid; idx < 16 * HSS; idx += 256) {
        int rr = idx >> 6, j = idx & 63;
        float acc = bs[j];
        for (int i = 0; i < HH; ++i) acc += s_mh[rr][i] * Ws[i * HSS + j];
        s_q[rr][j] = fmaxf(acc, 0.f);
    }
    __syncthreads();
    for (int idx = tid; idx < 16 * HH; idx += 256) {
        int rr = idx / HH, o = idx - rr * HH;
        float acc = brs[o];
#pragma unroll 8
        for (int j = 0; j < HSS; ++j) acc += s_q[rr][j] * Wrs[j * HH + o];
        float theme = 1.f / (1.f + expf(-acc));
        int r = r0 + rr;
        int b = b0 + rr;
        out[((size_t)b * TT + t) * HH + o] =
            theme * g_conv[(size_t)r * HH + o] + g_h[((size_t)t * BB + b) * HH + o];
    }
}

// ---------------- entry ----------------
extern "C" void kernel_launch(void* const* d_in, const int* in_sizes, int n_in,
                              void* d_out, int out_size) {
    (void)in_sizes; (void)n_in; (void)out_size;
    const float* x   = (const float*)d_in[0];
    const float* Wk  = (const float*)d_in[2];
    const float* bk  = (const float*)d_in[3];
    const float* Wr  = (const float*)d_in[4];
    const float* br  = (const float*)d_in[5];
    const float* Ws  = (const float*)d_in[6];
    const float* bs  = (const float*)d_in[7];
    const float* Wrs = (const float*)d_in[8];
    const float* brs = (const float*)d_in[9];
    const float* Wc  = (const float*)d_in[10];
    const float* bc  = (const float*)d_in[11];
    float* out = (float*)d_out;

    cudaFuncSetAttribute(k2_recurrent, cudaFuncAttributeMaxDynamicSharedMemorySize, K2_SMEM);

    k_prep_w<<<(int)(((size_t)NN * K3K + 255) / 256), 256>>>(Wc);
    k_prep_wk<<<(int)(((size_t)K1NP * K1K + 255) / 256), 256>>>(Wk);
    k_prep_wr<<<(int)(((size_t)K2NP * HH + 255) / 256), 256>>>(Wr);
    k_half_x<<<(int)(((size_t)NR * DD / 4 + 255) / 256), 256>>>(x);
    k1_gemm<<<dim3(13, 512), 256>>>(Wk, bk);
    k2_recurrent<<<K2_NB, 256, K2_SMEM>>>(Wr, br);
    k_dis<<<(NR + 255) / 256, 256>>>();
    k3_gemm<<<dim3(30, 512), 256>>>();
    k_gather<<<(int)(((size_t)NR * HH + 255) / 256), 256>>>(bc);
    k4_out<<<4096, 256>>>(Ws, bs, Wrs, brs, out);
}